// round 16
// baseline (speedup 1.0000x reference)
#include <cuda_runtime.h>
#include <cuda_bf16.h>

#define BATCH  4
#define NB     2048
#define NC     4
#define ROWSL  16          // u16 slots per row: [0]=count, [1..15]=neighbors
#define MAXDEG 15
#define NBINS  64
#define XSCALE 0.0625f     // fixed binning: bin = clamp((int)(x1/16), 0, 63)
#define BINW   16.0f
#define FGRID  128         // fused kernel blocks — all co-resident (<148 SMs)
#define FTPB   512
#define NSUB   32          // sort sub-blocks per batch (128/4), 64 boxes each

// __device__ scratch (allocation-free rule). uint4 => 32B-aligned rows.
__device__ uint4 g_adj_raw[(size_t)BATCH * NB * ROWSL / 8];
#define G_ADJ ((unsigned short*)g_adj_raw)
__device__ float4         g_sbox[BATCH * NB];      // bin-sorted boxes (by x1)
__device__ unsigned short g_sidx[BATCH * NB];      // sorted pos -> original idx
__device__ int            g_binoff[BATCH][NBINS + 1];
__device__ float          g_wmax[BATCH];           // per-batch max box width
__device__ int            g_bhist[BATCH][NSUB][NBINS];
__device__ float          g_bwmax[BATCH][NSUB];

// Grid barrier (replay-safe: gen monotone, cnt returns to 0).
__device__ unsigned           g_barcnt = 0;
__device__ volatile unsigned  g_bargen = 0;

__device__ __forceinline__ void gridbar() {
    __syncthreads();
    if (threadIdx.x == 0) {
        unsigned gen = g_bargen;
        __threadfence();
        unsigned t = atomicAdd(&g_barcnt, 1);
        if (t == FGRID - 1) {
            atomicExch(&g_barcnt, 0);
            __threadfence();
            g_bargen = gen + 1;
        } else {
            while (g_bargen == gen) { }
            __threadfence();
        }
    }
    __syncthreads();
}

// ---------------------------------------------------------------------------
// Fused K1: distributed counting sort + windowed adjacency. grid=128 x 512.
// Smem union (bytes): phase A small arrays alias the adj arrays.
//   adj:  sx1@0 sy1@8192 sx2@16384 sy2@24576 sar@32768, ssidx@40960,
//         sboff@45056 (260B), rowbox@45328, s_lo/hi@45584
//   sortA: hist@0, stot@256, smyb@512, sbase@768, boffA@1024, wred@1300
// ---------------------------------------------------------------------------
#define FS_SMEM 45600

__global__ void __launch_bounds__(FTPB) fused_kernel(const float4* __restrict__ boxes,
                                                     const float* __restrict__ thrp) {
    extern __shared__ unsigned char sm[];
    int tid = threadIdx.x, lane = tid & 31, warp = tid >> 5;
    int blk = blockIdx.x;
    int b   = blk >> 5;                  // batch (32 blocks per batch)
    int sub = blk & 31;                  // sort sub-block within batch
    float thr = thrp[0];

    // ================= PHASE A: histogram my 64 boxes =================
    {
        int*   shist = (int*)(sm + 0);
        float* swred = (float*)(sm + 1300);

        if (tid < NBINS) shist[tid] = 0;
        __syncthreads();

        float4 v; int bin = 0, rank = 0;
        if (tid < 64) {
            int i = sub * 64 + tid;
            v = boxes[(size_t)b * NB + i];
            bin = min(NBINS - 1, max(0, (int)(v.x * XSCALE)));
            rank = atomicAdd(&shist[bin], 1);
            float w = v.z - v.x;
            #pragma unroll
            for (int o = 16; o; o >>= 1)
                w = fmaxf(w, __shfl_xor_sync(0xffffffffu, w, o));
            if (lane == 0) swred[warp] = w;
        }
        __syncthreads();

        if (tid < NBINS) g_bhist[b][sub][tid] = shist[tid];
        if (tid == 0) g_bwmax[b][sub] = fmaxf(swred[0], swred[1]);

        gridbar();                       // publish hist + wmax partials

        // -------- scan + scatter --------
        int*   stot  = (int*)(sm + 256);
        int*   smyb  = (int*)(sm + 512);
        int*   sbase = (int*)(sm + 768);
        int*   boffA = (int*)(sm + 1024);

        if (tid < NBINS) {
            int acc = 0, myb = 0;
            #pragma unroll 8
            for (int s = 0; s < NSUB; s++) {
                int t = g_bhist[b][s][tid];
                if (s < sub) myb += t;
                acc += t;
            }
            stot[tid] = acc;
            smyb[tid] = myb;
        }
        __syncthreads();

        if (warp == 0) {                 // exclusive scan of 64 totals
            int a0 = stot[lane], a1 = stot[lane + 32];
            #pragma unroll
            for (int o = 1; o < 32; o <<= 1) {
                int n = __shfl_up_sync(0xffffffffu, a0, o);
                if (lane >= o) a0 += n;
            }
            int tot0 = __shfl_sync(0xffffffffu, a0, 31);
            #pragma unroll
            for (int o = 1; o < 32; o <<= 1) {
                int n = __shfl_up_sync(0xffffffffu, a1, o);
                if (lane >= o) a1 += n;
            }
            a1 += tot0;
            if (lane == 0) boffA[0] = 0;
            boffA[lane + 1] = a0;
            boffA[lane + 33] = a1;
        }
        __syncthreads();

        if (tid < NBINS) sbase[tid] = boffA[tid] + smyb[tid];
        __syncthreads();

        if (tid < 64) {
            int pos = sbase[bin] + rank;
            g_sbox[(size_t)b * NB + pos] = v;
            g_sidx[(size_t)b * NB + pos] = (unsigned short)(sub * 64 + tid);
        }
        if (sub == 0) {
            if (tid <= NBINS) g_binoff[b][tid] = boffA[tid];
            if (tid == 0) {
                float m = g_bwmax[b][0];
                #pragma unroll
                for (int s = 1; s < NSUB; s++) m = fmaxf(m, g_bwmax[b][s]);
                g_wmax[b] = fmaxf(m, 0.0f);
            }
        }
    }

    gridbar();                           // publish sorted boxes + binoff + wmax

    // ================= PHASE B: adjacency (4 tiles per block) =================
    {
        float* sx1 = (float*)(sm + 0);
        float* sy1 = (float*)(sm + 8192);
        float* sx2 = (float*)(sm + 16384);
        float* sy2 = (float*)(sm + 24576);
        float* sar = (float*)(sm + 32768);
        unsigned short* ssidx = (unsigned short*)(sm + 40960);
        int*    sboff  = (int*)(sm + 45056);
        float4* rowbox = (float4*)(sm + 45328);
        int*    slh    = (int*)(sm + 45584);

        float wmax = g_wmax[b];
        bool windowed = (thr >= 0.0f);   // hit => x-overlap only valid for thr>=0

        if (tid <= NBINS) sboff[tid] = g_binoff[b][tid];
        const float4* sb = g_sbox + (size_t)b * NB;

        for (int tt = 0; tt < 4; tt++) {
            int tilein = sub * 4 + tt;   // 0..127 within batch

            if (tid < 16) rowbox[tid] = sb[tilein * 16 + tid];
            __syncthreads();

            if (warp == 0) {
                float4 rv = rowbox[lane & 15];
                float r1 = rv.x, r2 = rv.z;
                #pragma unroll
                for (int o = 16; o; o >>= 1) {
                    r1 = fminf(r1, __shfl_xor_sync(0xffffffffu, r1, o));
                    r2 = fmaxf(r2, __shfl_xor_sync(0xffffffffu, r2, o));
                }
                if (lane == 0) {
                    int lo = 0, hi = NB;
                    if (windowed) {
                        int bl = min(NBINS - 1, max(0, (int)((r1 - wmax) * XSCALE) - 1));
                        int bh = min(NBINS, max(1, (int)(r2 * XSCALE) + 2));
                        lo = sboff[bl] & ~31;
                        hi = min(NB, (sboff[bh] + 31) & ~31);
                    }
                    slh[0] = lo; slh[1] = hi;
                }
            }
            __syncthreads();
            int lo = slh[0], hi = slh[1];

            for (int i = lo + tid; i < hi; i += FTPB) {
                float4 v = sb[i];
                int k = i - lo;
                sx1[k] = v.x; sy1[k] = v.y; sx2[k] = v.z; sy2[k] = v.w;
                sar[k] = (v.z - v.x) * (v.w - v.y);
                ssidx[k] = g_sidx[b * NB + i];
            }
            __syncthreads();

            int p = tilein * 16 + warp;  // sorted position of this row
            float4 rv = rowbox[warp];
            float rx1 = rv.x, ry1 = rv.y, rx2 = rv.z, ry2 = rv.w;
            float rar = (rx2 - rx1) * (ry2 - ry1);
            int orr = ssidx[p - lo];
            unsigned short* row = G_ADJ + (size_t)(b * NB + orr) * ROWSL;
            int cnt = 0;

            int c0 = lo >> 5;
            if (windowed) {
                int bl = min(NBINS - 1, max(0, (int)((rx1 - wmax) * XSCALE) - 1));
                c0 = max(c0, sboff[bl] >> 5);
            }

            for (int c = c0; c < (hi >> 5); c++) {
                if (windowed) {
                    float x1c = sx1[c * 32 - lo];
                    int bc = min(NBINS - 1, max(0, (int)(x1c * XSCALE)));
                    if ((float)(bc - 1) * BINW > rx2) break;   // bin-safe bound
                }
                int k = c * 32 + lane - lo;
                float ix = fminf(rx2, sx2[k]) - fmaxf(rx1, sx1[k]);
                float iy = fminf(ry2, sy2[k]) - fmaxf(ry1, sy1[k]);
                ix = fmaxf(ix, 0.0f);
                iy = fmaxf(iy, 0.0f);
                float inter = ix * iy;
                float unim  = fmaxf(rar + sar[k] - inter, 1e-6f);
                bool hit = (inter > thr * unim) && (c * 32 + lane != p);
                unsigned word = __ballot_sync(0xffffffffu, hit);
                if (lane == 0 && word) {
                    int base = c * 32 - lo;
                    while (word) {
                        int j = __ffs(word) - 1;
                        word &= word - 1u;
                        if (cnt < MAXDEG) row[1 + cnt] = ssidx[base + j];
                        cnt++;                   // exact count even if truncated
                    }
                }
            }
            if (lane == 0) row[0] = (unsigned short)cnt;
            __syncthreads();                     // smem reuse across tiles
        }
    }
}

// ---------------------------------------------------------------------------
// K2: lex-first-MIS greedy + integrated exact fallback. grid = BATCH*NC,
// 1024 thr. Rows in registers (2 nodes/thread); one barrier per round.
// ---------------------------------------------------------------------------
#define MS_KEY  0
#define MS_SBOX 0
#define MS_SAR  32768
#define MS_ST   40960
#define MS_CNT  43008
#define MS_SMEM 43040

__device__ __forceinline__ unsigned flipkey(float s) {
    unsigned u = __float_as_uint(s);
    return (u & 0x80000000u) ? ~u : (u | 0x80000000u);   // total order on floats
}

__global__ void __launch_bounds__(1024) mis_kernel(const float4* __restrict__ boxes,
                                                   const float* __restrict__ scores,
                                                   const float* __restrict__ thrp,
                                                   const float* __restrict__ sthrp,
                                                   float* __restrict__ out) {
    extern __shared__ unsigned char sm[];
    unsigned*               skey  = (unsigned*)(sm + MS_KEY);
    float4*                 fsbox = (float4*)(sm + MS_SBOX);
    float*                  fsar  = (float*)(sm + MS_SAR);
    volatile unsigned char* sst   = sm + MS_ST;
    volatile int*           scnt  = (int*)(sm + MS_CNT);

    int bc = blockIdx.x, b = bc >> 2;
    int tid = threadIdx.x, lane = tid & 31, warp = tid >> 5;
    float sthr = sthrp[0];
    bool selfm = thrp[0] < 1.0f;        // self-IoU = 1 claims self iff thr < 1
    const float* spc = scores + (size_t)bc * NB;
    float*       opc = out + (size_t)bc * NB;

    if (tid == 0) scnt[1] = 0;

    int n0 = tid, n1 = tid + 1024;
    ushort4 r0[4], r1[4];
    {
        const uint4* g0 = (const uint4*)(G_ADJ + (size_t)(b * NB + n0) * ROWSL);
        const uint4* g1 = (const uint4*)(G_ADJ + (size_t)(b * NB + n1) * ROWSL);
        uint4 a = g0[0], c = g1[0];
        r0[0] = *(ushort4*)&a.x; r0[1] = *(ushort4*)&a.z;
        uint4 a2 = g0[1], c2 = g1[1];
        r0[2] = *(ushort4*)&a2.x; r0[3] = *(ushort4*)&a2.z;
        r1[0] = *(ushort4*)&c.x; r1[1] = *(ushort4*)&c.z;
        r1[2] = *(ushort4*)&c2.x; r1[3] = *(ushort4*)&c2.z;
    }
    const unsigned short* e0 = (const unsigned short*)r0;
    const unsigned short* e1 = (const unsigned short*)r1;
    int d0 = e0[0], d1 = e1[0];
    if (d0 > MAXDEG || d1 > MAXDEG) scnt[1] = 1;

    float s0 = spc[n0], s1 = spc[n1];
    skey[n0] = flipkey(s0);
    skey[n1] = flipkey(s1);
    unsigned char st0, st1;
    if (s0 > sthr) { if (d0 == 0) { st0 = 3; opc[n0] = selfm ? (float)n0 : -1.0f; } else st0 = 0; }
    else           { st0 = 3; opc[n0] = -1.0f; }
    if (s1 > sthr) { if (d1 == 0) { st1 = 3; opc[n1] = selfm ? (float)n1 : -1.0f; } else st1 = 0; }
    else           { st1 = 3; opc[n1] = -1.0f; }
    sst[n0] = st0;
    sst[n1] = st1;
    __syncthreads();

    if (scnt[1] == 0) {
        bool u0 = (st0 == 0), u1 = (st1 == 0);
        for (int round = 0; round < 4096; round++) {
            if (u0) {
                unsigned mk = skey[n0];
                bool blocked = false, claimed = false;
                #pragma unroll
                for (int e = 1; e <= MAXDEG; e++) {
                    if (e > d0) break;
                    int u = e0[e];
                    unsigned char stu = sst[u];
                    if (stu >= 2) continue;
                    unsigned fu = skey[u];
                    bool hp = (fu > mk) || (fu == mk && u < n0);
                    if (!hp) continue;
                    if (stu == 1) { claimed = true; break; }
                    blocked = true;
                }
                if (claimed)       { sst[n0] = 2; u0 = false; }
                else if (!blocked) { sst[n0] = 1; u0 = false; }
            }
            if (u1) {
                unsigned mk = skey[n1];
                bool blocked = false, claimed = false;
                #pragma unroll
                for (int e = 1; e <= MAXDEG; e++) {
                    if (e > d1) break;
                    int u = e1[e];
                    unsigned char stu = sst[u];
                    if (stu >= 2) continue;
                    unsigned fu = skey[u];
                    bool hp = (fu > mk) || (fu == mk && u < n1);
                    if (!hp) continue;
                    if (stu == 1) { claimed = true; break; }
                    blocked = true;
                }
                if (claimed)       { sst[n1] = 2; u1 = false; }
                else if (!blocked) { sst[n1] = 1; u1 = false; }
            }
            if (u0 | u1) scnt[0] = round + 1;        // benign race: same value
            __syncthreads();
            if (scnt[0] != round + 1) break;
        }

        unsigned char f0 = sst[n0], f1 = sst[n1];
        if (f0 == 1) opc[n0] = (float)n0;
        else if (f0 == 2) {
            unsigned bk = 0; int bu = -1;
            #pragma unroll
            for (int e = 1; e <= MAXDEG; e++) {
                if (e > d0) break;
                int u = e0[e];
                if (sst[u] == 1) {
                    unsigned fu = skey[u];
                    if (bu < 0 || fu > bk || (fu == bk && u < bu)) { bk = fu; bu = u; }
                }
            }
            opc[n0] = (float)bu;
        }
        if (f1 == 1) opc[n1] = (float)n1;
        else if (f1 == 2) {
            unsigned bk = 0; int bu = -1;
            #pragma unroll
            for (int e = 1; e <= MAXDEG; e++) {
                if (e > d1) break;
                int u = e1[e];
                if (sst[u] == 1) {
                    unsigned fu = skey[u];
                    if (bu < 0 || fu > bk || (fu == bk && u < bu)) { bk = fu; bu = u; }
                }
            }
            opc[n1] = (float)bu;
        }
        return;
    }

    // ---- integrated exact fallback for THIS (b,c) (adversarial only) ----
    {
        float thr = thrp[0];
        const float4* bb = boxes + (size_t)b * NB;
        for (int i = tid; i < NB; i += 1024) {
            float4 v = bb[i];
            fsbox[i] = v;
            fsar[i] = (v.z - v.x) * (v.w - v.y);
        }
        for (int n = tid; n < NB; n += 1024) {
            sst[n] = (spc[n] > sthr) ? 0 : 1;
            opc[n] = -1.0f;
        }
        __syncthreads();

        if (warp == 0) {
            for (;;) {
                float bs = -1e30f; int bi = 1 << 30;
                for (int k = 0; k < NB / 32; k++) {
                    int u = k * 32 + lane;
                    if (!sst[u]) {
                        float s = spc[u];
                        if (s > bs || (s == bs && u < bi)) { bs = s; bi = u; }
                    }
                }
                #pragma unroll
                for (int off = 16; off; off >>= 1) {
                    float os = __shfl_down_sync(0xffffffffu, bs, off);
                    int   oi = __shfl_down_sync(0xffffffffu, bi, off);
                    if (os > bs || (os == bs && oi < bi)) { bs = os; bi = oi; }
                }
                bi = __shfl_sync(0xffffffffu, bi, 0);
                if (bi >= (1 << 30)) break;

                float4 tb = fsbox[bi];
                float tar = fsar[bi];
                float lf = (float)bi;
                for (int k = 0; k < NB / 32; k++) {
                    int u = k * 32 + lane;
                    if (!sst[u]) {
                        float4 ub = fsbox[u];
                        float ix = fminf(tb.z, ub.z) - fmaxf(tb.x, ub.x);
                        float iy = fminf(tb.w, ub.w) - fmaxf(tb.y, ub.y);
                        ix = fmaxf(ix, 0.0f);
                        iy = fmaxf(iy, 0.0f);
                        float inter = ix * iy;
                        float unim  = fmaxf(tar + fsar[u] - inter, 1e-6f);
                        if (inter > thr * unim) { sst[u] = 1; opc[u] = lf; }
                    }
                }
                if (lane == 0) sst[bi] = 1;
                __syncwarp();
            }
        }
    }
}

// ---------------------------------------------------------------------------
extern "C" void kernel_launch(void* const* d_in, const int* in_sizes, int n_in,
                              void* d_out, int out_size) {
    const float4* boxes  = (const float4*)d_in[0];
    const float*  scores = (const float*)d_in[1];
    const float*  iouthr = (const float*)d_in[2];
    const float*  scothr = (const float*)d_in[3];
    float* out = (float*)d_out;

    cudaFuncSetAttribute(fused_kernel,
                         cudaFuncAttributeMaxDynamicSharedMemorySize, FS_SMEM);
    cudaFuncSetAttribute(mis_kernel,
                         cudaFuncAttributeMaxDynamicSharedMemorySize, MS_SMEM);

    fused_kernel<<<FGRID, FTPB, FS_SMEM>>>(boxes, iouthr);
    mis_kernel<<<BATCH * NC, 1024, MS_SMEM>>>(boxes, scores, iouthr, scothr, out);
}

// round 17
// speedup vs baseline: 1.3431x; 1.3431x over previous
#include <cuda_runtime.h>
#include <cuda_bf16.h>

#define BATCH  4
#define NB     2048
#define NC     4
#define ROWSL  16          // u16 slots per row: [0]=count, [1..15]=neighbors
#define MAXDEG 15
#define NBINS  64
#define XSCALE 0.0625f     // fixed binning: bin = clamp((int)(x1/16), 0, 63)
#define BINW   16.0f
#define SGRID  32          // sort blocks (8 per batch) — all co-resident
#define STPB   256

// __device__ scratch (allocation-free rule). uint4 => 32B-aligned rows.
__device__ uint4 g_adj_raw[(size_t)BATCH * NB * ROWSL / 8];
#define G_ADJ ((unsigned short*)g_adj_raw)
__device__ float4         g_sbox[BATCH * NB];      // bin-sorted boxes (by x1)
__device__ unsigned short g_sidx[BATCH * NB];      // sorted pos -> original idx
__device__ int            g_binoff[BATCH][NBINS + 1];
__device__ float          g_wmax[BATCH];           // per-batch max box width
__device__ int            g_bhist[BATCH][8][NBINS];
__device__ float          g_bwmax[BATCH][8];

// Grid barrier (replay-safe: gen monotone, cnt returns to 0). 32 blocks only.
__device__ unsigned           g_barcnt = 0;
__device__ volatile unsigned  g_bargen = 0;

__device__ __forceinline__ void gridbar32() {
    __syncthreads();
    if (threadIdx.x == 0) {
        unsigned gen = g_bargen;
        __threadfence();
        unsigned t = atomicAdd(&g_barcnt, 1);
        if (t == SGRID - 1) {
            atomicExch(&g_barcnt, 0);
            __threadfence();
            g_bargen = gen + 1;
        } else {
            while (g_bargen == gen) { }
            __threadfence();
        }
    }
    __syncthreads();
}

// ---------------------------------------------------------------------------
// K0: distributed counting sort. grid = 32, block = 256, 1 box/thread.
// ---------------------------------------------------------------------------
__global__ void __launch_bounds__(STPB) sort_kernel(const float4* __restrict__ boxes) {
    __shared__ int   shist[NBINS];
    __shared__ int   stot[NBINS], smyb[NBINS], sbase[NBINS];
    __shared__ int   sboff[NBINS + 1];
    __shared__ float swred[8];

    int blk = blockIdx.x;
    int b = blk >> 3, sub = blk & 7;
    int tid = threadIdx.x, lane = tid & 31, warp = tid >> 5;

    if (tid < NBINS) shist[tid] = 0;
    __syncthreads();

    int i = sub * STPB + tid;                       // box index in batch
    float4 v = boxes[(size_t)b * NB + i];
    int bin = min(NBINS - 1, max(0, (int)(v.x * XSCALE)));
    int rank = atomicAdd(&shist[bin], 1);           // rank within (block, bin)

    float w = v.z - v.x;
    #pragma unroll
    for (int o = 16; o; o >>= 1)
        w = fmaxf(w, __shfl_xor_sync(0xffffffffu, w, o));
    if (lane == 0) swred[warp] = w;
    __syncthreads();

    if (tid < NBINS) g_bhist[b][sub][tid] = shist[tid];
    if (tid == 0) {
        float m = swred[0];
        #pragma unroll
        for (int j = 1; j < 8; j++) m = fmaxf(m, swred[j]);
        g_bwmax[b][sub] = m;
    }

    gridbar32();                                    // fences publish g_bhist/g_bwmax

    if (tid < NBINS) {
        int acc = 0, myb = 0;
        #pragma unroll
        for (int s = 0; s < 8; s++) {
            int t = g_bhist[b][s][tid];
            if (s < sub) myb += t;
            acc += t;
        }
        stot[tid] = acc;
        smyb[tid] = myb;
    }
    __syncthreads();

    if (warp == 0) {                                // exclusive scan of 64 totals
        int a0 = stot[lane], a1 = stot[lane + 32];
        #pragma unroll
        for (int o = 1; o < 32; o <<= 1) {
            int n = __shfl_up_sync(0xffffffffu, a0, o);
            if (lane >= o) a0 += n;
        }
        int tot0 = __shfl_sync(0xffffffffu, a0, 31);
        #pragma unroll
        for (int o = 1; o < 32; o <<= 1) {
            int n = __shfl_up_sync(0xffffffffu, a1, o);
            if (lane >= o) a1 += n;
        }
        a1 += tot0;
        if (lane == 0) sboff[0] = 0;
        sboff[lane + 1] = a0;
        sboff[lane + 33] = a1;
    }
    __syncthreads();

    if (tid < NBINS) sbase[tid] = sboff[tid] + smyb[tid];
    __syncthreads();

    int pos = sbase[bin] + rank;
    g_sbox[(size_t)b * NB + pos] = v;
    g_sidx[(size_t)b * NB + pos] = (unsigned short)i;

    if (sub == 0) {
        if (tid <= NBINS) g_binoff[b][tid] = sboff[tid];
        if (tid == 0) {
            float m = g_bwmax[b][0];
            #pragma unroll
            for (int s = 1; s < 8; s++) m = fmaxf(m, g_bwmax[b][s]);
            g_wmax[b] = fmaxf(m, 0.0f);
        }
    }
}

// ---------------------------------------------------------------------------
// K1: adjacency rows over bin-sorted boxes. 512 blocks x 512 thr, 16 rows.
// PDL consumer: gridDepSync before reading sort outputs.
// ---------------------------------------------------------------------------
__global__ void __launch_bounds__(512) adj_kernel(const float* __restrict__ thrp) {
    __shared__ float sx1[NB], sy1[NB], sx2[NB], sy2[NB], sar[NB];
    __shared__ unsigned short ssidx[NB];
    __shared__ int sboff[NBINS + 1];
    __shared__ float4 rowbox[16];
    __shared__ int s_lo, s_hi;

    int b    = blockIdx.x >> 7;
    int tile = blockIdx.x & 127;
    int tid  = threadIdx.x;
    int warp = tid >> 5, lane = tid & 31;

    float thr  = thrp[0];                // host input: safe pre-sync
    bool windowed = (thr >= 0.0f);

    cudaGridDependencySynchronize();     // sort outputs ready beyond this point

    float wmax = g_wmax[b];
    if (tid <= NBINS) sboff[tid] = g_binoff[b][tid];
    if (tid < 16) rowbox[tid] = g_sbox[b * NB + tile * 16 + tid];
    __syncthreads();

    if (warp == 0) {
        float4 rv = rowbox[lane & 15];
        float r1 = rv.x, r2 = rv.z;
        #pragma unroll
        for (int o = 16; o; o >>= 1) {
            r1 = fminf(r1, __shfl_xor_sync(0xffffffffu, r1, o));
            r2 = fmaxf(r2, __shfl_xor_sync(0xffffffffu, r2, o));
        }
        if (lane == 0) {
            int lo = 0, hi = NB;
            if (windowed) {
                int bl = min(NBINS - 1, max(0, (int)((r1 - wmax) * XSCALE) - 1));
                int bh = min(NBINS, max(1, (int)(r2 * XSCALE) + 2));
                lo = sboff[bl] & ~31;
                hi = min(NB, (sboff[bh] + 31) & ~31);
            }
            s_lo = lo; s_hi = hi;
        }
    }
    __syncthreads();
    int lo = s_lo, hi = s_hi;

    const float4* sb = g_sbox + (size_t)b * NB;
    for (int i = lo + tid; i < hi; i += 512) {
        float4 v = sb[i];
        int k = i - lo;
        sx1[k] = v.x; sy1[k] = v.y; sx2[k] = v.z; sy2[k] = v.w;
        sar[k] = (v.z - v.x) * (v.w - v.y);
        ssidx[k] = g_sidx[b * NB + i];
    }
    __syncthreads();

    int p = tile * 16 + warp;            // sorted position of this row
    float4 rv = rowbox[warp];
    float rx1 = rv.x, ry1 = rv.y, rx2 = rv.z, ry2 = rv.w;
    float rar = (rx2 - rx1) * (ry2 - ry1);
    int orr = ssidx[p - lo];
    unsigned short* row = G_ADJ + (size_t)(b * NB + orr) * ROWSL;
    int cnt = 0;

    int c0 = lo >> 5;
    if (windowed) {
        int bl = min(NBINS - 1, max(0, (int)((rx1 - wmax) * XSCALE) - 1));
        c0 = max(c0, sboff[bl] >> 5);
    }

    for (int c = c0; c < (hi >> 5); c++) {
        if (windowed) {
            float x1c = sx1[c * 32 - lo];
            int bc = min(NBINS - 1, max(0, (int)(x1c * XSCALE)));
            if ((float)(bc - 1) * BINW > rx2) break;   // bin-safe lower bound
        }
        int k = c * 32 + lane - lo;
        float ix = fminf(rx2, sx2[k]) - fmaxf(rx1, sx1[k]);
        float iy = fminf(ry2, sy2[k]) - fmaxf(ry1, sy1[k]);
        ix = fmaxf(ix, 0.0f);
        iy = fmaxf(iy, 0.0f);
        float inter = ix * iy;
        float unim  = fmaxf(rar + sar[k] - inter, 1e-6f);
        bool hit = (inter > thr * unim) && (c * 32 + lane != p);   // drop self
        unsigned word = __ballot_sync(0xffffffffu, hit);
        if (lane == 0 && word) {
            int base = c * 32 - lo;
            while (word) {
                int j = __ffs(word) - 1;
                word &= word - 1u;
                if (cnt < MAXDEG) row[1 + cnt] = ssidx[base + j];
                cnt++;                                  // exact count even if truncated
            }
        }
    }
    if (lane == 0) row[0] = (unsigned short)cnt;
}

// ---------------------------------------------------------------------------
// K2: lex-first-MIS greedy + integrated exact fallback. grid = BATCH*NC,
// 1024 thr. PDL consumer: scores/flipkey prologue BEFORE gridDepSync; all
// G_ADJ-dependent work after.
// ---------------------------------------------------------------------------
#define MS_KEY  0
#define MS_SBOX 0
#define MS_SAR  32768
#define MS_ST   40960
#define MS_CNT  43008
#define MS_SMEM 43040

__device__ __forceinline__ unsigned flipkey(float s) {
    unsigned u = __float_as_uint(s);
    return (u & 0x80000000u) ? ~u : (u | 0x80000000u);   // total order on floats
}

__global__ void __launch_bounds__(1024) mis_kernel(const float4* __restrict__ boxes,
                                                   const float* __restrict__ scores,
                                                   const float* __restrict__ thrp,
                                                   const float* __restrict__ sthrp,
                                                   float* __restrict__ out) {
    extern __shared__ unsigned char sm[];
    unsigned*               skey  = (unsigned*)(sm + MS_KEY);
    float4*                 fsbox = (float4*)(sm + MS_SBOX);
    float*                  fsar  = (float*)(sm + MS_SAR);
    volatile unsigned char* sst   = sm + MS_ST;
    volatile int*           scnt  = (int*)(sm + MS_CNT);

    int bc = blockIdx.x, b = bc >> 2;
    int tid = threadIdx.x, lane = tid & 31, warp = tid >> 5;

    // ---------- prologue: independent of predecessor kernels ----------
    float sthr = sthrp[0];
    bool selfm = thrp[0] < 1.0f;        // self-IoU = 1 claims self iff thr < 1
    const float* spc = scores + (size_t)bc * NB;
    float*       opc = out + (size_t)bc * NB;

    if (tid == 0) scnt[1] = 0;

    int n0 = tid, n1 = tid + 1024;
    float s0 = spc[n0], s1 = spc[n1];   // host inputs: safe pre-sync
    skey[n0] = flipkey(s0);
    skey[n1] = flipkey(s1);

    cudaGridDependencySynchronize();     // G_ADJ ready beyond this point

    // ---------- epilogue of init: needs adjacency ----------
    ushort4 r0[4], r1[4];
    {
        const uint4* g0 = (const uint4*)(G_ADJ + (size_t)(b * NB + n0) * ROWSL);
        const uint4* g1 = (const uint4*)(G_ADJ + (size_t)(b * NB + n1) * ROWSL);
        uint4 a = g0[0], c = g1[0];
        r0[0] = *(ushort4*)&a.x; r0[1] = *(ushort4*)&a.z;
        uint4 a2 = g0[1], c2 = g1[1];
        r0[2] = *(ushort4*)&a2.x; r0[3] = *(ushort4*)&a2.z;
        r1[0] = *(ushort4*)&c.x; r1[1] = *(ushort4*)&c.z;
        r1[2] = *(ushort4*)&c2.x; r1[3] = *(ushort4*)&c2.z;
    }
    const unsigned short* e0 = (const unsigned short*)r0;
    const unsigned short* e1 = (const unsigned short*)r1;
    int d0 = e0[0], d1 = e1[0];
    if (d0 > MAXDEG || d1 > MAXDEG) scnt[1] = 1;

    unsigned char st0, st1;
    if (s0 > sthr) { if (d0 == 0) { st0 = 3; opc[n0] = selfm ? (float)n0 : -1.0f; } else st0 = 0; }
    else           { st0 = 3; opc[n0] = -1.0f; }
    if (s1 > sthr) { if (d1 == 0) { st1 = 3; opc[n1] = selfm ? (float)n1 : -1.0f; } else st1 = 0; }
    else           { st1 = 3; opc[n1] = -1.0f; }
    sst[n0] = st0;
    sst[n1] = st1;
    __syncthreads();

    if (scnt[1] == 0) {
        bool u0 = (st0 == 0), u1 = (st1 == 0);
        for (int round = 0; round < 4096; round++) {
            if (u0) {
                unsigned mk = skey[n0];
                bool blocked = false, claimed = false;
                #pragma unroll
                for (int e = 1; e <= MAXDEG; e++) {
                    if (e > d0) break;
                    int u = e0[e];
                    unsigned char stu = sst[u];
                    if (stu >= 2) continue;
                    unsigned fu = skey[u];
                    bool hp = (fu > mk) || (fu == mk && u < n0);
                    if (!hp) continue;
                    if (stu == 1) { claimed = true; break; }
                    blocked = true;
                }
                if (claimed)       { sst[n0] = 2; u0 = false; }
                else if (!blocked) { sst[n0] = 1; u0 = false; }
            }
            if (u1) {
                unsigned mk = skey[n1];
                bool blocked = false, claimed = false;
                #pragma unroll
                for (int e = 1; e <= MAXDEG; e++) {
                    if (e > d1) break;
                    int u = e1[e];
                    unsigned char stu = sst[u];
                    if (stu >= 2) continue;
                    unsigned fu = skey[u];
                    bool hp = (fu > mk) || (fu == mk && u < n1);
                    if (!hp) continue;
                    if (stu == 1) { claimed = true; break; }
                    blocked = true;
                }
                if (claimed)       { sst[n1] = 2; u1 = false; }
                else if (!blocked) { sst[n1] = 1; u1 = false; }
            }
            if (u0 | u1) scnt[0] = round + 1;        // benign race: same value
            __syncthreads();
            if (scnt[0] != round + 1) break;
        }

        unsigned char f0 = sst[n0], f1 = sst[n1];
        if (f0 == 1) opc[n0] = (float)n0;
        else if (f0 == 2) {
            unsigned bk = 0; int bu = -1;
            #pragma unroll
            for (int e = 1; e <= MAXDEG; e++) {
                if (e > d0) break;
                int u = e0[e];
                if (sst[u] == 1) {
                    unsigned fu = skey[u];
                    if (bu < 0 || fu > bk || (fu == bk && u < bu)) { bk = fu; bu = u; }
                }
            }
            opc[n0] = (float)bu;
        }
        if (f1 == 1) opc[n1] = (float)n1;
        else if (f1 == 2) {
            unsigned bk = 0; int bu = -1;
            #pragma unroll
            for (int e = 1; e <= MAXDEG; e++) {
                if (e > d1) break;
                int u = e1[e];
                if (sst[u] == 1) {
                    unsigned fu = skey[u];
                    if (bu < 0 || fu > bk || (fu == bk && u < bu)) { bk = fu; bu = u; }
                }
            }
            opc[n1] = (float)bu;
        }
        return;
    }

    // ---- integrated exact fallback for THIS (b,c) (adversarial only) ----
    {
        float thr = thrp[0];
        const float4* bb = boxes + (size_t)b * NB;
        for (int i = tid; i < NB; i += 1024) {
            float4 v = bb[i];
            fsbox[i] = v;
            fsar[i] = (v.z - v.x) * (v.w - v.y);
        }
        for (int n = tid; n < NB; n += 1024) {
            sst[n] = (spc[n] > sthr) ? 0 : 1;
            opc[n] = -1.0f;
        }
        __syncthreads();

        if (warp == 0) {
            for (;;) {
                float bs = -1e30f; int bi = 1 << 30;
                for (int k = 0; k < NB / 32; k++) {
                    int u = k * 32 + lane;
                    if (!sst[u]) {
                        float s = spc[u];
                        if (s > bs || (s == bs && u < bi)) { bs = s; bi = u; }
                    }
                }
                #pragma unroll
                for (int off = 16; off; off >>= 1) {
                    float os = __shfl_down_sync(0xffffffffu, bs, off);
                    int   oi = __shfl_down_sync(0xffffffffu, bi, off);
                    if (os > bs || (os == bs && oi < bi)) { bs = os; bi = oi; }
                }
                bi = __shfl_sync(0xffffffffu, bi, 0);
                if (bi >= (1 << 30)) break;

                float4 tb = fsbox[bi];
                float tar = fsar[bi];
                float lf = (float)bi;
                for (int k = 0; k < NB / 32; k++) {
                    int u = k * 32 + lane;
                    if (!sst[u]) {
                        float4 ub = fsbox[u];
                        float ix = fminf(tb.z, ub.z) - fmaxf(tb.x, ub.x);
                        float iy = fminf(tb.w, ub.w) - fmaxf(tb.y, ub.y);
                        ix = fmaxf(ix, 0.0f);
                        iy = fmaxf(iy, 0.0f);
                        float inter = ix * iy;
                        float unim  = fmaxf(tar + fsar[u] - inter, 1e-6f);
                        if (inter > thr * unim) { sst[u] = 1; opc[u] = lf; }
                    }
                }
                if (lane == 0) sst[bi] = 1;
                __syncwarp();
            }
        }
    }
}

// ---------------------------------------------------------------------------
extern "C" void kernel_launch(void* const* d_in, const int* in_sizes, int n_in,
                              void* d_out, int out_size) {
    const float4* boxes  = (const float4*)d_in[0];
    const float*  scores = (const float*)d_in[1];
    const float*  iouthr = (const float*)d_in[2];
    const float*  scothr = (const float*)d_in[3];
    float* out = (float*)d_out;

    cudaFuncSetAttribute(mis_kernel, cudaFuncAttributeMaxDynamicSharedMemorySize, MS_SMEM);

    sort_kernel<<<SGRID, STPB>>>(boxes);

    cudaLaunchAttribute pdl[1];
    pdl[0].id = cudaLaunchAttributeProgrammaticStreamSerialization;
    pdl[0].val.programmaticStreamSerializationAllowed = 1;

    {   // adj with PDL overlap
        cudaLaunchConfig_t cfg = {};
        cfg.gridDim = dim3(BATCH * 128);
        cfg.blockDim = dim3(512);
        cfg.dynamicSmemBytes = 0;
        cfg.stream = 0;
        cfg.attrs = pdl;
        cfg.numAttrs = 1;
        cudaLaunchKernelEx(&cfg, adj_kernel, iouthr);
    }
    {   // mis with PDL overlap
        cudaLaunchConfig_t cfg = {};
        cfg.gridDim = dim3(BATCH * NC);
        cfg.blockDim = dim3(1024);
        cfg.dynamicSmemBytes = MS_SMEM;
        cfg.stream = 0;
        cfg.attrs = pdl;
        cfg.numAttrs = 1;
        cudaLaunchKernelEx(&cfg, mis_kernel, boxes, scores, iouthr, scothr, out);
    }
}